// round 3
// baseline (speedup 1.0000x reference)
#include <cuda_runtime.h>
#include <math.h>

// ---------------- problem constants ----------------
#define BB     2        // batch
#define EE     256      // encoder channels
#define DD     512      // bottleneck channels
#define T_IN   64000    // input samples
#define FK     20       // encoder/decoder kernel
#define STRIDE 10
#define TC     6403     // encoder frames: (64000 + 40 - 20)/10 + 1
#define TS     6404     // padded time stride (multiple of 4 for float4 alignment)
#define NL     6        // layers per block
#define NBLK   2        // blocks
#define KDW    3        // depthwise kernel
#define BNEPS  1e-5f

// ---------------- scratch (device globals; no allocs allowed) ----------------
__device__ float g_enc[BB * EE * TS];
__device__ float g_hA [BB * EE * TS];
__device__ float g_hB [BB * EE * TS];
__device__ float g_t1 [BB * DD * TS];   // D-channel scratch / mask buffer
__device__ float g_t2 [BB * DD * TS];

// Buffer ids: 0=enc 1=hA 2=hB 3=t1 4=t2
__device__ __forceinline__ float* buf_ptr(int id) {
    switch (id) {
        case 0: return g_enc;
        case 1: return g_hA;
        case 2: return g_hB;
        case 3: return g_t1;
        default: return g_t2;
    }
}

// ---------------- encoder: Conv1d(1,E,20,stride=10,pad=20) -> g_enc ----------
__global__ void encoder_k(const float* __restrict__ x,
                          const float* __restrict__ ew,
                          const float* __restrict__ eb)
{
    int idx = blockIdx.x * blockDim.x + threadIdx.x;
    if (idx >= BB * EE * TS) return;
    int t = idx % TS;
    int ce = idx / TS;
    int e = ce % EE;
    int b = ce / EE;
    if (t >= TC) return;
    const float* xr = x + b * T_IN;
    const float* w  = ew + e * FK;
    float acc = __ldg(&eb[e]);
    int p0 = t * STRIDE - FK;
    #pragma unroll
    for (int k = 0; k < FK; k++) {
        int p = p0 + k;
        if (p >= 0 && p < T_IN) acc += __ldg(&w[k]) * __ldg(&xr[p]);
    }
    g_enc[idx] = acc;
}

// ---------------- fused 1x1-conv GEMM ----------------
// Y[b][m][t] = epilogue( sum_k W[m][k] * X[b][k][t] + bias[m] )
// mode 0: prelu(alpha) then BN(g,be,mn,vr)     (conv1 path)
// mode 1: bias only                            (conv2 mid-layer)
// mode 2: bias + residual add                  (conv2 last layer of block)
#define BM 128
#define BN 128
#define BK 8

__global__ __launch_bounds__(256)
void gemm_fused(const float* __restrict__ W,   // [M, Kdim]
                int xid, int yid, int rid,
                int M, int Kdim,
                const float* __restrict__ bias,
                int mode,
                const float* __restrict__ alpha_p,
                const float* __restrict__ bn_g,
                const float* __restrict__ bn_b,
                const float* __restrict__ bn_m,
                const float* __restrict__ bn_v)
{
    const float* X = buf_ptr(xid);
    float*       Y = buf_ptr(yid);

    const int b  = blockIdx.z;
    const int n0 = blockIdx.x * BN;
    const int m0 = blockIdx.y * BM;
    const float* Xb = X + (size_t)b * Kdim * TS;
    float* Yb       = Y + (size_t)b * M    * TS;

    __shared__ float Ws[BK][BM];
    __shared__ float Xs[BK][BN];

    const int tid = threadIdx.x;           // 256 threads
    const int wr = tid >> 1;               // 0..127  (row of W tile)
    const int wc = (tid & 1) * 4;          // 0 or 4  (k offset)
    const int xk = tid >> 5;               // 0..7
    const int xn = (tid & 31) * 4;         // 0..124
    const int tx = tid & 15;
    const int ty = tid >> 4;

    float acc[8][8];
    #pragma unroll
    for (int i = 0; i < 8; i++)
        #pragma unroll
        for (int j = 0; j < 8; j++) acc[i][j] = 0.f;

    for (int k0 = 0; k0 < Kdim; k0 += BK) {
        // W tile (transposed store into smem)
        float4 wv = *reinterpret_cast<const float4*>(&W[(size_t)(m0 + wr) * Kdim + k0 + wc]);
        Ws[wc + 0][wr] = wv.x;
        Ws[wc + 1][wr] = wv.y;
        Ws[wc + 2][wr] = wv.z;
        Ws[wc + 3][wr] = wv.w;
        // X tile
        int ncol = n0 + xn;
        const float* xrow = &Xb[(size_t)(k0 + xk) * TS];
        float4 xv;
        if (ncol + 3 < TC) {
            xv = *reinterpret_cast<const float4*>(&xrow[ncol]);
        } else {
            xv.x = (ncol + 0 < TC) ? xrow[ncol + 0] : 0.f;
            xv.y = (ncol + 1 < TC) ? xrow[ncol + 1] : 0.f;
            xv.z = (ncol + 2 < TC) ? xrow[ncol + 2] : 0.f;
            xv.w = (ncol + 3 < TC) ? xrow[ncol + 3] : 0.f;
        }
        *reinterpret_cast<float4*>(&Xs[xk][xn]) = xv;
        __syncthreads();

        #pragma unroll
        for (int kk = 0; kk < BK; kk++) {
            float4 a0 = *reinterpret_cast<const float4*>(&Ws[kk][ty * 4]);
            float4 a1 = *reinterpret_cast<const float4*>(&Ws[kk][ty * 4 + 64]);
            float4 b0 = *reinterpret_cast<const float4*>(&Xs[kk][tx * 4]);
            float4 b1 = *reinterpret_cast<const float4*>(&Xs[kk][tx * 4 + 64]);
            float av[8] = {a0.x, a0.y, a0.z, a0.w, a1.x, a1.y, a1.z, a1.w};
            float bv[8] = {b0.x, b0.y, b0.z, b0.w, b1.x, b1.y, b1.z, b1.w};
            #pragma unroll
            for (int i = 0; i < 8; i++)
                #pragma unroll
                for (int j = 0; j < 8; j++)
                    acc[i][j] = fmaf(av[i], bv[j], acc[i][j]);
        }
        __syncthreads();
    }

    const float al = (mode == 0) ? __ldg(&alpha_p[0]) : 0.f;
    const float* R = (mode == 2) ? buf_ptr(rid) : nullptr;

    #pragma unroll
    for (int i = 0; i < 8; i++) {
        int mrow = m0 + ty * 4 + ((i < 4) ? i : (60 + i));   // ty*4+i or ty*4+64+(i-4)
        float bia = __ldg(&bias[mrow]);
        float sc = 1.f, sh = 0.f;
        if (mode == 0) {
            sc = __ldg(&bn_g[mrow]) * rsqrtf(__ldg(&bn_v[mrow]) + BNEPS);
            sh = __ldg(&bn_b[mrow]) - __ldg(&bn_m[mrow]) * sc;
        }
        float* yrow = &Yb[(size_t)mrow * TS];
        const float* rrow = (mode == 2) ? &R[((size_t)b * M + mrow) * TS] : nullptr;
        #pragma unroll
        for (int j = 0; j < 8; j++) {
            int n = n0 + tx * 4 + ((j < 4) ? j : (60 + j));
            if (n < TC) {
                float v = acc[i][j] + bia;
                if (mode == 0) {
                    v = (v > 0.f) ? v : al * v;
                    v = v * sc + sh;
                } else if (mode == 2) {
                    v += rrow[n];
                }
                yrow[n] = v;
            }
        }
    }
}

// ---------------- depthwise K=3 dilated conv + PReLU + BN  (g_t1 -> g_t2) ----
__global__ void dw_fused(const float* __restrict__ wd, const float* __restrict__ bd,
                         const float* __restrict__ alpha_p,
                         const float* __restrict__ g, const float* __restrict__ be,
                         const float* __restrict__ mn, const float* __restrict__ vr,
                         int dil)
{
    int idx = blockIdx.x * blockDim.x + threadIdx.x;
    if (idx >= BB * DD * TS) return;
    int t  = idx % TS;
    int cd = idx / TS;
    int d  = cd % DD;
    if (t >= TC) return;
    const float* xr = g_t1 + (size_t)cd * TS;
    float w0 = __ldg(&wd[d * 3 + 0]), w1 = __ldg(&wd[d * 3 + 1]), w2 = __ldg(&wd[d * 3 + 2]);
    float acc = __ldg(&bd[d]) + w1 * xr[t];
    if (t - dil >= 0) acc += w0 * xr[t - dil];
    if (t + dil < TC) acc += w2 * xr[t + dil];
    float al = __ldg(&alpha_p[0]);
    acc = (acc > 0.f) ? acc : al * acc;
    float sc = __ldg(&g[d]) * rsqrtf(__ldg(&vr[d]) + BNEPS);
    g_t2[idx] = (acc - __ldg(&mn[d])) * sc + __ldg(&be[d]);
}

// ---------------- mask: g_t1 = g_enc * sigmoid(g_hB) ----------------
__global__ void mask_k()
{
    int idx = blockIdx.x * blockDim.x + threadIdx.x;
    if (idx >= BB * EE * TS) return;
    int t = idx % TS;
    if (t >= TC) return;
    float hv = g_hB[idx];
    float s = 1.f / (1.f + expf(-hv));
    g_t1[idx] = g_enc[idx] * s;
}

// ---------------- decoder: ConvTranspose1d(E,1,20,stride=10), slice [FK:T+FK] ---
// out[b][t] = dec_b + sum_e mask[b][e][t1]*w[e][k1] + mask[b][e][t2]*w[e][k2]
//   m = t+FK; t1 = m/10; k1 = m%10; t2 = t1-1; k2 = k1+10  (always in-range here)
__global__ void decoder_k(const float* __restrict__ dw,
                          const float* __restrict__ db,
                          float* __restrict__ out)
{
    int idx = blockIdx.x * blockDim.x + threadIdx.x;
    if (idx >= BB * T_IN) return;
    int t = idx % T_IN;
    int b = idx / T_IN;
    int m  = t + FK;
    int t1 = m / STRIDE;
    int k1 = m - t1 * STRIDE;
    int t2 = t1 - 1;
    int k2 = k1 + STRIDE;
    const float* mb = g_t1 + (size_t)b * EE * TS;
    float acc = __ldg(&db[0]);
    #pragma unroll 4
    for (int e = 0; e < EE; e++) {
        const float* mr = &mb[(size_t)e * TS];
        const float* wr = &dw[e * FK];
        acc = fmaf(mr[t1], __ldg(&wr[k1]), acc);
        acc = fmaf(mr[t2], __ldg(&wr[k2]), acc);
    }
    out[idx] = acc;
}

// ---------------- launch (kernel launches ONLY) ----------------
extern "C" void kernel_launch(void* const* d_in, const int* in_sizes, int n_in,
                              void* d_out, int out_size)
{
    const float* x     = (const float*)d_in[0];
    const float* enc_w = (const float*)d_in[1];
    const float* enc_b = (const float*)d_in[2];
    const float* w1    = (const float*)d_in[3];
    const float* b1    = (const float*)d_in[4];
    const float* a1    = (const float*)d_in[5];
    const float* g1    = (const float*)d_in[6];
    const float* be1   = (const float*)d_in[7];
    const float* m1    = (const float*)d_in[8];
    const float* v1    = (const float*)d_in[9];
    const float* wd    = (const float*)d_in[10];
    const float* bd    = (const float*)d_in[11];
    const float* a2    = (const float*)d_in[12];
    const float* g2    = (const float*)d_in[13];
    const float* be2   = (const float*)d_in[14];
    const float* m2    = (const float*)d_in[15];
    const float* v2    = (const float*)d_in[16];
    const float* w2    = (const float*)d_in[17];
    const float* b2    = (const float*)d_in[18];
    const float* dec_w = (const float*)d_in[19];
    const float* dec_b = (const float*)d_in[20];
    float* out = (float*)d_out;

    const int nE = BB * EE * TS;
    const int nD = BB * DD * TS;

    encoder_k<<<(nE + 255) / 256, 256>>>(x, enc_w, enc_b);

    const int NT = (TC + BN - 1) / BN;   // 51 time tiles

    for (int bI = 0; bI < NBLK; bI++) {
        const int blk_in = (bI == 0) ? 0 : 1;   // block input == residual source (enc or hA)
        const int hbuf   = (bI == 0) ? 1 : 2;   // working h buffer (hA or hB)
        for (int i = 0; i < NL; i++) {
            int off = bI * NL + i;
            int in = (i == 0) ? blk_in : hbuf;
            // conv1: E->D, prelu+bn   (in -> t1)
            dim3 gg1(NT, DD / BM, BB);
            gemm_fused<<<gg1, 256>>>(w1 + (size_t)off * DD * EE, in, 3, 0,
                                     DD, EE, b1 + (size_t)off * DD, 0,
                                     a1 + off,
                                     g1 + (size_t)off * DD, be1 + (size_t)off * DD,
                                     m1 + (size_t)off * DD, v1 + (size_t)off * DD);
            // depthwise + prelu + bn  (t1 -> t2)
            dw_fused<<<(nD + 255) / 256, 256>>>(wd + (size_t)off * DD * KDW,
                                                bd + (size_t)off * DD,
                                                a2 + off,
                                                g2 + (size_t)off * DD, be2 + (size_t)off * DD,
                                                m2 + (size_t)off * DD, v2 + (size_t)off * DD,
                                                1 << i);
            // conv2: D->E (+ residual on last layer)  (t2 -> hbuf)
            int mode = (i == NL - 1) ? 2 : 1;
            dim3 gg2(NT, EE / BM, BB);
            gemm_fused<<<gg2, 256>>>(w2 + (size_t)off * EE * DD, 4, hbuf, blk_in,
                                     EE, DD, b2 + (size_t)off * EE, mode,
                                     nullptr, nullptr, nullptr, nullptr, nullptr);
        }
    }

    // mask + decode (mask stored into g_t1 scratch, E-channel layout)
    mask_k<<<(nE + 255) / 256, 256>>>();
    decoder_k<<<(BB * T_IN + 255) / 256, 256>>>(dec_w, dec_b, out);
}

// round 5
// speedup vs baseline: 1.0263x; 1.0263x over previous
#include <cuda_runtime.h>
#include <math.h>

// ---------------- problem constants ----------------
#define BB     2        // batch
#define EE     256      // encoder channels
#define DD     512      // bottleneck channels
#define T_IN   64000    // input samples
#define FK     20       // encoder/decoder kernel
#define STRIDE 10
#define TC     6403     // encoder frames: (64000 + 40 - 20)/10 + 1
#define TS     6404     // padded time stride (multiple of 4 for float4 alignment)
#define NL     6        // layers per block
#define NBLK   2        // blocks
#define KDW    3        // depthwise kernel
#define BNEPS  1e-5f

// ---------------- scratch (device globals; no allocs allowed) ----------------
__device__ float g_enc[BB * EE * TS];
__device__ float g_hA [BB * EE * TS];
__device__ float g_hB [BB * EE * TS];
__device__ float g_t1 [BB * DD * TS];   // D-channel scratch / mask buffer
__device__ float g_t2 [BB * DD * TS];

// Buffer ids: 0=enc 1=hA 2=hB 3=t1 4=t2
__device__ __forceinline__ float* buf_ptr(int id) {
    switch (id) {
        case 0: return g_enc;
        case 1: return g_hA;
        case 2: return g_hB;
        case 3: return g_t1;
        default: return g_t2;
    }
}

// packed f32x2 FMA: d = a*b + d (elementwise on 2 packed floats)
__device__ __forceinline__ void ffma2(unsigned long long& d,
                                      unsigned long long a,
                                      unsigned long long b) {
    asm("fma.rn.f32x2 %0, %1, %2, %0;" : "+l"(d) : "l"(a), "l"(b));
}

// ---------------- encoder: Conv1d(1,E,20,stride=10,pad=20) -> g_enc ----------
__global__ void encoder_k(const float* __restrict__ x,
                          const float* __restrict__ ew,
                          const float* __restrict__ eb)
{
    int idx = blockIdx.x * blockDim.x + threadIdx.x;
    if (idx >= BB * EE * TS) return;
    int t = idx % TS;
    int ce = idx / TS;
    int e = ce % EE;
    int b = ce / EE;
    if (t >= TC) return;
    const float* xr = x + b * T_IN;
    const float* w  = ew + e * FK;
    float acc = __ldg(&eb[e]);
    int p0 = t * STRIDE - FK;
    #pragma unroll
    for (int k = 0; k < FK; k++) {
        int p = p0 + k;
        if (p >= 0 && p < T_IN) acc += __ldg(&w[k]) * __ldg(&xr[p]);
    }
    g_enc[idx] = acc;
}

// ---------------- fused 1x1-conv GEMM (double-buffered, FFMA2) --------------
// Y[b][m][t] = epilogue( sum_k W[m][k] * X[b][k][t] + bias[m] )
// mode 0: prelu(alpha) then BN           (conv1 path)
// mode 1: bias only                      (conv2 mid-layer)
// mode 2: bias + residual add            (conv2 last layer of block 0)
// mode 3: bias + residual, then masked = enc * sigmoid(.)  (final conv2)
#define BM 128
#define BN 64
#define BK 8

__global__ __launch_bounds__(256, 3)
void gemm_fused(const float* __restrict__ W,   // [M, Kdim]
                int xid, int yid, int rid,
                int M, int Kdim,
                const float* __restrict__ bias,
                int mode,
                const float* __restrict__ alpha_p,
                const float* __restrict__ bn_g,
                const float* __restrict__ bn_b,
                const float* __restrict__ bn_m,
                const float* __restrict__ bn_v)
{
    const float* X = buf_ptr(xid);
    float*       Y = buf_ptr(yid);

    const int b  = blockIdx.z;
    const int n0 = blockIdx.x * BN;
    const int m0 = blockIdx.y * BM;
    const float* Xb = X + (size_t)b * Kdim * TS;

    // W tile stored DUPLICATED ([v,v] pairs) so compute reads pre-packed f32x2.
    // 16-byte aligned: these are reinterpreted as 64-bit packed operands.
    __shared__ __align__(16) float Ws[2][BK][2 * BM];   // 16 KB
    __shared__ __align__(16) float Xs[2][BK][BN];       //  4 KB

    const int tid = threadIdx.x;          // 256 threads
    // W-load mapping
    const int wr = tid >> 1;              // 0..127 row
    const int wc = (tid & 1) * 4;         // 0 or 4 (k offset)
    // X-load mapping
    const int xk = tid >> 5;              // 0..7
    const int xn = (tid & 31) * 2;        // 0..62
    // compute mapping: 8 rows x 4 cols per thread
    const int tx = tid & 15;              // N
    const int ty = tid >> 4;              // M

    const float* wptr = &W[(size_t)(m0 + wr) * Kdim + wc];
    const int xcol = n0 + xn;

    unsigned long long acc[8][2];
    #pragma unroll
    for (int i = 0; i < 8; i++) { acc[i][0] = 0ULL; acc[i][1] = 0ULL; }

    const int ktiles = Kdim / BK;

    // ---- prologue: tile 0 ----
    {
        float4 wv = *reinterpret_cast<const float4*>(wptr);
        Ws[0][wc + 0][2 * wr] = wv.x;  Ws[0][wc + 0][2 * wr + 1] = wv.x;
        Ws[0][wc + 1][2 * wr] = wv.y;  Ws[0][wc + 1][2 * wr + 1] = wv.y;
        Ws[0][wc + 2][2 * wr] = wv.z;  Ws[0][wc + 2][2 * wr + 1] = wv.z;
        Ws[0][wc + 3][2 * wr] = wv.w;  Ws[0][wc + 3][2 * wr + 1] = wv.w;
        const float* xr = &Xb[(size_t)xk * TS];
        float2 xv;
        if (xcol + 1 < TC) xv = *reinterpret_cast<const float2*>(&xr[xcol]);
        else { xv.x = (xcol < TC) ? xr[xcol] : 0.f; xv.y = 0.f; }
        *reinterpret_cast<float2*>(&Xs[0][xk][xn]) = xv;
    }
    __syncthreads();

    for (int kt = 0; kt < ktiles; kt++) {
        const int cur = kt & 1;
        const bool has_next = (kt + 1 < ktiles);
        float4 wv; float2 xv;
        if (has_next) {
            wv = *reinterpret_cast<const float4*>(wptr + (kt + 1) * BK);
            const float* xr = &Xb[(size_t)((kt + 1) * BK + xk) * TS];
            if (xcol + 1 < TC) xv = *reinterpret_cast<const float2*>(&xr[xcol]);
            else { xv.x = (xcol < TC) ? xr[xcol] : 0.f; xv.y = 0.f; }
        }

        #pragma unroll
        for (int kk = 0; kk < BK; kk++) {
            const unsigned long long* arow =
                reinterpret_cast<const unsigned long long*>(&Ws[cur][kk][16 * ty]);
            const unsigned long long* brow =
                reinterpret_cast<const unsigned long long*>(&Xs[cur][kk][4 * tx]);
            unsigned long long b0 = brow[0];
            unsigned long long b1 = brow[1];
            #pragma unroll
            for (int i = 0; i < 8; i++) {
                unsigned long long a = arow[i];
                ffma2(acc[i][0], a, b0);
                ffma2(acc[i][1], a, b1);
            }
        }

        if (has_next) {
            const int nb = cur ^ 1;
            Ws[nb][wc + 0][2 * wr] = wv.x;  Ws[nb][wc + 0][2 * wr + 1] = wv.x;
            Ws[nb][wc + 1][2 * wr] = wv.y;  Ws[nb][wc + 1][2 * wr + 1] = wv.y;
            Ws[nb][wc + 2][2 * wr] = wv.z;  Ws[nb][wc + 2][2 * wr + 1] = wv.z;
            Ws[nb][wc + 3][2 * wr] = wv.w;  Ws[nb][wc + 3][2 * wr + 1] = wv.w;
            *reinterpret_cast<float2*>(&Xs[nb][xk][xn]) = xv;
            __syncthreads();
        }
    }

    // ---- epilogue ----
    const float al = (mode == 0) ? __ldg(&alpha_p[0]) : 0.f;
    const float* R = (mode >= 2) ? buf_ptr(rid) : nullptr;

    #pragma unroll
    for (int i = 0; i < 8; i++) {
        const int mrow = m0 + ty * 8 + i;
        const float bia = __ldg(&bias[mrow]);
        float sc = 1.f, sh = 0.f;
        if (mode == 0) {
            sc = __ldg(&bn_g[mrow]) * rsqrtf(__ldg(&bn_v[mrow]) + BNEPS);
            sh = __ldg(&bn_b[mrow]) - __ldg(&bn_m[mrow]) * sc;
        }
        float* yrow = &Y[((size_t)b * M + mrow) * TS];
        const float* rrow = (mode >= 2) ? &R[((size_t)b * M + mrow) * TS] : nullptr;
        const float* erow = (mode == 3) ? &g_enc[((size_t)b * EE + mrow) * TS] : nullptr;

        float2 p0 = *reinterpret_cast<float2*>(&acc[i][0]);
        float2 p1 = *reinterpret_cast<float2*>(&acc[i][1]);
        float v[4] = {p0.x, p0.y, p1.x, p1.y};
        const int n = n0 + tx * 4;

        #pragma unroll
        for (int j = 0; j < 4; j++) {
            if (n + j >= TC) continue;
            float t = v[j] + bia;
            if (mode == 0) {
                t = (t > 0.f) ? t : al * t;
                t = t * sc + sh;
            } else if (mode == 2) {
                t += rrow[n + j];
            } else if (mode == 3) {
                t += rrow[n + j];
                float s = 1.f / (1.f + expf(-t));
                t = erow[n + j] * s;
            }
            v[j] = t;
        }

        if (n + 3 < TC) {
            float4 o = {v[0], v[1], v[2], v[3]};
            *reinterpret_cast<float4*>(&yrow[n]) = o;
        } else {
            #pragma unroll
            for (int j = 0; j < 4; j++)
                if (n + j < TC) yrow[n + j] = v[j];
        }
    }
}

// ---------------- depthwise K=3 dilated conv + PReLU + BN  (g_t1 -> g_t2) ----
__global__ void dw_fused(const float* __restrict__ wd, const float* __restrict__ bd,
                         const float* __restrict__ alpha_p,
                         const float* __restrict__ g, const float* __restrict__ be,
                         const float* __restrict__ mn, const float* __restrict__ vr,
                         int dil)
{
    int idx = blockIdx.x * blockDim.x + threadIdx.x;
    if (idx >= BB * DD * TS) return;
    int t  = idx % TS;
    int cd = idx / TS;
    int d  = cd % DD;
    if (t >= TC) return;
    const float* xr = g_t1 + (size_t)cd * TS;
    float w0 = __ldg(&wd[d * 3 + 0]), w1 = __ldg(&wd[d * 3 + 1]), w2 = __ldg(&wd[d * 3 + 2]);
    float acc = __ldg(&bd[d]) + w1 * xr[t];
    if (t - dil >= 0) acc += w0 * xr[t - dil];
    if (t + dil < TC) acc += w2 * xr[t + dil];
    float al = __ldg(&alpha_p[0]);
    acc = (acc > 0.f) ? acc : al * acc;
    float sc = __ldg(&g[d]) * rsqrtf(__ldg(&vr[d]) + BNEPS);
    g_t2[idx] = (acc - __ldg(&mn[d])) * sc + __ldg(&be[d]);
}

// ---------------- decoder: ConvTranspose1d(E,1,20,stride=10), slice [FK:T+FK] ---
// out[b][t] = dec_b + sum_e mask[b][e][t1]*w[e][k1] + mask[b][e][t2]*w[e][k2]
//   m = t+FK; t1 = m/10; k1 = m%10; t2 = t1-1; k2 = k1+10  (always in-range here)
__global__ void decoder_k(const float* __restrict__ dw,
                          const float* __restrict__ db,
                          float* __restrict__ out)
{
    int idx = blockIdx.x * blockDim.x + threadIdx.x;
    if (idx >= BB * T_IN) return;
    int t = idx % T_IN;
    int b = idx / T_IN;
    int m  = t + FK;
    int t1 = m / STRIDE;
    int k1 = m - t1 * STRIDE;
    int t2 = t1 - 1;
    int k2 = k1 + STRIDE;
    const float* mb = g_t1 + (size_t)b * EE * TS;
    float acc = __ldg(&db[0]);
    #pragma unroll 4
    for (int e = 0; e < EE; e++) {
        const float* mr = &mb[(size_t)e * TS];
        const float* wr = &dw[e * FK];
        acc = fmaf(mr[t1], __ldg(&wr[k1]), acc);
        acc = fmaf(mr[t2], __ldg(&wr[k2]), acc);
    }
    out[idx] = acc;
}

// ---------------- launch (kernel launches ONLY) ----------------
extern "C" void kernel_launch(void* const* d_in, const int* in_sizes, int n_in,
                              void* d_out, int out_size)
{
    const float* x     = (const float*)d_in[0];
    const float* enc_w = (const float*)d_in[1];
    const float* enc_b = (const float*)d_in[2];
    const float* w1    = (const float*)d_in[3];
    const float* b1    = (const float*)d_in[4];
    const float* a1    = (const float*)d_in[5];
    const float* g1    = (const float*)d_in[6];
    const float* be1   = (const float*)d_in[7];
    const float* m1    = (const float*)d_in[8];
    const float* v1    = (const float*)d_in[9];
    const float* wd    = (const float*)d_in[10];
    const float* bd    = (const float*)d_in[11];
    const float* a2    = (const float*)d_in[12];
    const float* g2    = (const float*)d_in[13];
    const float* be2   = (const float*)d_in[14];
    const float* m2    = (const float*)d_in[15];
    const float* v2    = (const float*)d_in[16];
    const float* w2    = (const float*)d_in[17];
    const float* b2    = (const float*)d_in[18];
    const float* dec_w = (const float*)d_in[19];
    const float* dec_b = (const float*)d_in[20];
    float* out = (float*)d_out;

    const int nE = BB * EE * TS;
    const int nD = BB * DD * TS;

    encoder_k<<<(nE + 255) / 256, 256>>>(x, enc_w, enc_b);

    const int NT = (TC + BN - 1) / BN;   // 101 time tiles

    for (int bI = 0; bI < NBLK; bI++) {
        const int blk_in = (bI == 0) ? 0 : 1;   // block input == residual source (enc or hA)
        const int hbuf   = (bI == 0) ? 1 : 2;   // working h buffer (hA or hB)
        for (int i = 0; i < NL; i++) {
            int off = bI * NL + i;
            int in = (i == 0) ? blk_in : hbuf;
            // conv1: E->D, prelu+bn   (in -> t1)
            dim3 gg1(NT, DD / BM, BB);
            gemm_fused<<<gg1, 256>>>(w1 + (size_t)off * DD * EE, in, 3, 0,
                                     DD, EE, b1 + (size_t)off * DD, 0,
                                     a1 + off,
                                     g1 + (size_t)off * DD, be1 + (size_t)off * DD,
                                     m1 + (size_t)off * DD, v1 + (size_t)off * DD);
            // depthwise + prelu + bn  (t1 -> t2)
            dw_fused<<<(nD + 255) / 256, 256>>>(wd + (size_t)off * DD * KDW,
                                                bd + (size_t)off * DD,
                                                a2 + off,
                                                g2 + (size_t)off * DD, be2 + (size_t)off * DD,
                                                m2 + (size_t)off * DD, v2 + (size_t)off * DD,
                                                1 << i);
            // conv2: D->E  (t2 -> hbuf); last layer adds residual;
            // very last layer also applies sigmoid-mask vs enc and writes g_t1
            int mode = (i == NL - 1) ? ((bI == NBLK - 1) ? 3 : 2) : 1;
            int yid  = (mode == 3) ? 3 : hbuf;
            dim3 gg2(NT, EE / BM, BB);
            gemm_fused<<<gg2, 256>>>(w2 + (size_t)off * EE * DD, 4, yid, blk_in,
                                     EE, DD, b2 + (size_t)off * EE, mode,
                                     nullptr, nullptr, nullptr, nullptr, nullptr);
        }
    }

    // decode (mask already fused into final conv2 -> g_t1)
    decoder_k<<<(BB * T_IN + 255) / 256, 256>>>(dec_w, dec_b, out);
}